// round 5
// baseline (speedup 1.0000x reference)
#include <cuda_runtime.h>
#include <cstddef>

#define SEQ   512
#define BATCH 4096
#define INDIM 9
#define HID   64
#define OUTD  10
#define NTH   128
#define CSCALE 2.885390081777927f      // 2/ln2
#define WSCALE (-2.0f * CSCALE)

// shared memory float offsets (all 256B aligned blocks)
#define O_HIST  0                          // (SEQ+2)*HID : xw' rows -> r2 history; rows 512,513 dummy
#define O_XS    (O_HIST + (SEQ+2)*HID)     // SEQ*INDIM
#define O_R1    (O_XS + SEQ*INDIM)         // 2*HID
#define O_R2    (O_R1 + 2*HID)             // 2*HID
#define O_PI    (O_R2 + 2*HID)             // [2][64] ull = 4*HID floats
#define O_RS1   (O_PI + 4*HID)             // HID
#define O_WFC   (O_RS1 + HID)              // OUTD*HID (scaled by -2)
#define O_BFC   (O_WFC + OUTD*HID)         // 16
#define SM_FLOATS (O_BFC + 16)
#define SM_BYTES  (SM_FLOATS * 4)

typedef unsigned long long ull;

__device__ __forceinline__ ull ffma2(ull a, ull b, ull c) {
    ull d; asm("fma.rn.f32x2 %0, %1, %2, %3;" : "=l"(d) : "l"(a), "l"(b), "l"(c));
    return d;
}
__device__ __forceinline__ ull fadd2(ull a, ull b) {
    ull d; asm("add.rn.f32x2 %0, %1, %2;" : "=l"(d) : "l"(a), "l"(b));
    return d;
}
__device__ __forceinline__ float f2sum(ull a) {
    float2 f = *reinterpret_cast<float2*>(&a);
    return f.x + f.y;
}
__device__ __forceinline__ ull pack2(float x, float y) {
    ull r; asm("mov.b64 %0, {%1,%2};" : "=l"(r) : "f"(x), "f"(y));
    return r;
}
// r = 1/(e^{2s}+1) with input pre-scaled by 2/ln2; tanh(s) = 1 - 2r
__device__ __forceinline__ float sig_r(float in) {
    float e, r;
    asm("ex2.approx.f32 %0, %1;" : "=f"(e) : "f"(in));
    asm("rcp.approx.f32 %0, %1;" : "=f"(r) : "f"(e + 1.0f));
    return r;
}
#define BAR128() asm volatile("bar.sync 0, 128;" ::: "memory")

// 32-long half dot (16 ffma2, 4 accums): w[16] . src[0:32]
__device__ __forceinline__ ull half_dot(const ull* __restrict__ w,
                                        const float* __restrict__ src) {
    const ulonglong2* hp = reinterpret_cast<const ulonglong2*>(src);
    ull b0 = 0ull, b1 = 0ull, b2 = 0ull, b3 = 0ull;
    #pragma unroll
    for (int q = 0; q < 4; ++q) {
        ulonglong2 u = hp[2*q], v = hp[2*q+1];
        b0 = ffma2(u.x, w[4*q+0], b0);
        b1 = ffma2(u.y, w[4*q+1], b1);
        b2 = ffma2(v.x, w[4*q+2], b2);
        b3 = ffma2(v.y, w[4*q+3], b3);
    }
    return fadd2(fadd2(b0, b1), fadd2(b2, b3));
}

// layer1: r1(it) = sig(w1.r1(it-1) + xw'); pIA(it-1) = wi2[0:32].r1(it-1)[0:32]
__device__ __forceinline__ void l1_body(const ull* __restrict__ w1,
                                        const ull* __restrict__ wi2h,
                                        const float* __restrict__ r1src, float xw,
                                        float* __restrict__ r1dst,
                                        ull* __restrict__ piAdst) {
    const ulonglong2* hp = reinterpret_cast<const ulonglong2*>(r1src);
    ull a0=0ull, a1=0ull, a2=0ull, a3=0ull, b0=0ull, b1=0ull;
    #pragma unroll
    for (int q = 0; q < 8; ++q) {
        ulonglong2 u = hp[q];
        a0 = ffma2(u.x, w1[2*q],    a0);
        a1 = ffma2(u.y, w1[2*q+1],  a1);
        b0 = ffma2(u.x, wi2h[2*q],   b0);
        b1 = ffma2(u.y, wi2h[2*q+1], b1);
    }
    *piAdst = fadd2(b0, b1);                    // off critical path: store early
    #pragma unroll
    for (int q = 8; q < 16; ++q) {
        ulonglong2 u = hp[q];
        a2 = ffma2(u.x, w1[2*q],   a2);
        a3 = ffma2(u.y, w1[2*q+1], a3);
    }
    ull sa = fadd2(fadd2(a0, a2), fadd2(a1, a3));
    *r1dst = sig_r(f2sum(sa) + xw);
}

// layer2: r2 = sig(base2 + piA + pibCarry + wh.r2prev); returns next carry
__device__ __forceinline__ ull l2_body(const ull* __restrict__ wh,
                                       const ull* __restrict__ wi2h,
                                       const float* __restrict__ r2src,
                                       const float* __restrict__ r1half,
                                       const ull* __restrict__ piAsrc,
                                       ull pibCarry, float base2,
                                       float* __restrict__ r2dst,
                                       float* __restrict__ histdst) {
    const ulonglong2* hp = reinterpret_cast<const ulonglong2*>(r2src);
    ull c0=0ull, c1=0ull, c2=0ull, c3=0ull;
    #pragma unroll
    for (int q = 0; q < 8; ++q) {
        ulonglong2 u = hp[q];
        c0 = ffma2(u.x, wh[2*q],   c0);
        c1 = ffma2(u.y, wh[2*q+1], c1);
    }
    #pragma unroll
    for (int q = 8; q < 16; ++q) {
        ulonglong2 u = hp[q];
        c2 = ffma2(u.x, wh[2*q],   c2);
        c3 = ffma2(u.y, wh[2*q+1], c3);
    }
    ull piA = *piAsrc;
    ull sc = fadd2(fadd2(c0, c2), fadd2(c1, c3));
    sc = fadd2(sc, fadd2(piA, pibCarry));
    float r = sig_r(f2sum(sc) + base2);
    *r2dst   = r;
    *histdst = r;
    return half_dot(wi2h, r1half);              // carry for next step (off path)
}

__global__ __launch_bounds__(NTH, 1)
void rnn_motion_kernel(const float* __restrict__ x,
                       const float* __restrict__ Wih0, const float* __restrict__ Whh0,
                       const float* __restrict__ bih0, const float* __restrict__ bhh0,
                       const float* __restrict__ Wih1, const float* __restrict__ Whh1,
                       const float* __restrict__ bih1, const float* __restrict__ bhh1,
                       const float* __restrict__ Wfc,  const float* __restrict__ bfc_g,
                       float* __restrict__ out)
{
    extern __shared__ float sm[];
    float* hist = sm + O_HIST;
    float* xs   = sm + O_XS;
    float* r1b  = sm + O_R1;
    float* r2b  = sm + O_R2;
    ull*   pib  = reinterpret_cast<ull*>(sm + O_PI);   // [2][64]
    float* rs1  = sm + O_RS1;
    float* wfc  = sm + O_WFC;
    float* bfc  = sm + O_BFC;

    const int tid = threadIdx.x;

    // ---- prologue A ----
    for (int e = tid; e < SEQ*INDIM; e += NTH) {
        int t = e / INDIM, k = e % INDIM;
        xs[e] = x[((size_t)t * BATCH + (BATCH - 1)) * INDIM + k];
    }
    for (int e = tid; e < OUTD*HID; e += NTH) wfc[e] = -2.0f * Wfc[e];
    hist[SEQ*HID + tid] = 0.0f;                         // dummy rows 512,513
    if (tid < HID) {
        r1b[tid] = 0.5f; r1b[HID+tid] = 0.5f;           // h = 0  <->  r = 0.5
        r2b[tid] = 0.5f; r2b[HID+tid] = 0.5f;
        const float4* p = reinterpret_cast<const float4*>(Whh0 + (size_t)tid * HID);
        float s = 0.f;
        #pragma unroll
        for (int q = 0; q < 16; ++q) { float4 v = p[q]; s += (v.x+v.y)+(v.z+v.w); }
        rs1[tid] = s;                                   // rowsum(Whh0_i)
    }
    if (tid < OUTD) {                                   // bfc'[o] = bfc + rowsum(Wfc_o)
        const float4* p = reinterpret_cast<const float4*>(Wfc + (size_t)tid * HID);
        float s = bfc_g[tid];
        #pragma unroll
        for (int q = 0; q < 16; ++q) { float4 v = p[q]; s += (v.x+v.y)+(v.z+v.w); }
        bfc[tid] = s;
    }
    __syncthreads();

    // ---- prologue B: xw'[t][i] = C*(x_t.Wih0_i + b_ih0 + b_hh0 + rowsum(Whh0_i)) ----
    {
        const int ii = tid & (HID-1);
        float wi[INDIM];
        #pragma unroll
        for (int k = 0; k < INDIM; ++k) wi[k] = CSCALE * Wih0[ii*INDIM + k];
        const float bb = CSCALE * (bih0[ii] + bhh0[ii] + rs1[ii]);
        for (int t = tid >> 6; t < SEQ; t += NTH/HID) {
            float s = bb;
            #pragma unroll
            for (int k = 0; k < INDIM; ++k) s += xs[t*INDIM + k] * wi[k];
            hist[t*HID + ii] = s;
        }
    }
    __syncthreads();

    // ---- pipelined scan: it = 0..513, BAR once per it ----
    if (tid < HID) {
        // ===== layer1 warps =====
        const int i = tid;
        ull w1[32], wi2h[16];
        {
            const float4* p = reinterpret_cast<const float4*>(Whh0 + (size_t)i * HID);
            #pragma unroll
            for (int q = 0; q < 16; ++q) {
                float4 v = p[q];
                w1[2*q]   = pack2(v.x*WSCALE, v.y*WSCALE);
                w1[2*q+1] = pack2(v.z*WSCALE, v.w*WSCALE);
            }
            const float4* p2 = reinterpret_cast<const float4*>(Wih1 + (size_t)i * HID);
            #pragma unroll
            for (int q = 0; q < 8; ++q) {          // first half [0:32]
                float4 v = p2[q];
                wi2h[2*q]   = pack2(v.x*WSCALE, v.y*WSCALE);
                wi2h[2*q+1] = pack2(v.z*WSCALE, v.w*WSCALE);
            }
        }
        // peel it=0,1
        l1_body(w1, wi2h, r1b,       hist[i],     &r1b[HID+i], &pib[HID+i]);  BAR128();
        l1_body(w1, wi2h, r1b + HID, hist[HID+i], &r1b[i],     &pib[i]);      BAR128();
        const float* xwp = hist + 2*HID + i;
        #pragma unroll 1
        for (int k2 = 0; k2 < SEQ/2; ++k2) {
            l1_body(w1, wi2h, r1b,       xwp[0],   &r1b[HID+i], &pib[HID+i]); BAR128();
            l1_body(w1, wi2h, r1b + HID, xwp[HID], &r1b[i],     &pib[i]);     BAR128();
            xwp += 2*HID;
        }
    } else {
        // ===== layer2 warps =====
        const int i = tid - HID;
        ull wh[32], wi2h[16];
        float rsH = 0.f, rsI = 0.f;
        {
            const float4* p = reinterpret_cast<const float4*>(Whh1 + (size_t)i * HID);
            #pragma unroll
            for (int q = 0; q < 16; ++q) {
                float4 v = p[q];
                rsH += (v.x+v.y)+(v.z+v.w);
                wh[2*q]   = pack2(v.x*WSCALE, v.y*WSCALE);
                wh[2*q+1] = pack2(v.z*WSCALE, v.w*WSCALE);
            }
            const float4* p2 = reinterpret_cast<const float4*>(Wih1 + (size_t)i * HID);
            #pragma unroll
            for (int q = 0; q < 16; ++q) {
                float4 v = p2[q];
                rsI += (v.x+v.y)+(v.z+v.w);
                if (q >= 8) {                      // second half [32:64]
                    wi2h[2*(q-8)]   = pack2(v.x*WSCALE, v.y*WSCALE);
                    wi2h[2*(q-8)+1] = pack2(v.z*WSCALE, v.w*WSCALE);
                }
            }
        }
        const float base2 = CSCALE * (bih1[i] + bhh1[i] + rsI + rsH);
        BAR128();                                          // it=0
        ull carry = half_dot(wi2h, r1b + HID + 32);        // pIB(0) from r1(0)[32:64]
        BAR128();                                          // it=1
        float* hw = hist + i;
        #pragma unroll 1
        for (int k2 = 0; k2 < SEQ/2; ++k2) {
            carry = l2_body(wh, wi2h, r2b,       r1b + 32,       &pib[i],
                            carry, base2, &r2b[HID+i], hw);            BAR128();
            carry = l2_body(wh, wi2h, r2b + HID, r1b + HID + 32, &pib[HID+i],
                            carry, base2, &r2b[i],     hw + HID);      BAR128();
            hw += 2*HID;
        }
    }
    __syncthreads();

    // ---- epilogue: out[t][o] = bfc'[o] + sum_k r2[t][k] * (-2*Wfc[o][k]) ----
    #pragma unroll
    for (int m = 0; m < SEQ/NTH; ++m) {
        const int t = tid + NTH * m;
        const float4* h4 = reinterpret_cast<const float4*>(hist + t*HID);
        #pragma unroll
        for (int o = 0; o < OUTD; ++o) {
            const float4* w4 = reinterpret_cast<const float4*>(wfc + o*HID);
            float s0 = bfc[o], s1 = 0.f, s2 = 0.f, s3 = 0.f;
            #pragma unroll
            for (int q = 0; q < HID/4; ++q) {
                float4 h = h4[q], w = w4[q];
                s0 = fmaf(h.x, w.x, s0);
                s1 = fmaf(h.y, w.y, s1);
                s2 = fmaf(h.z, w.z, s2);
                s3 = fmaf(h.w, w.w, s3);
            }
            out[t*OUTD + o] = (s0 + s1) + (s2 + s3);
        }
    }
}

extern "C" void kernel_launch(void* const* d_in, const int* in_sizes, int n_in,
                              void* d_out, int out_size) {
    (void)in_sizes; (void)n_in; (void)out_size;
    const float* x    = (const float*)d_in[0];
    const float* Wih0 = (const float*)d_in[1];
    const float* Whh0 = (const float*)d_in[2];
    const float* bih0 = (const float*)d_in[3];
    const float* bhh0 = (const float*)d_in[4];
    const float* Wih1 = (const float*)d_in[5];
    const float* Whh1 = (const float*)d_in[6];
    const float* bih1 = (const float*)d_in[7];
    const float* bhh1 = (const float*)d_in[8];
    const float* Wfc  = (const float*)d_in[9];
    const float* bfc  = (const float*)d_in[10];
    float* out = (float*)d_out;

    cudaFuncSetAttribute(rnn_motion_kernel,
                         cudaFuncAttributeMaxDynamicSharedMemorySize, SM_BYTES);
    rnn_motion_kernel<<<1, NTH, SM_BYTES>>>(
        x, Wih0, Whh0, bih0, bhh0, Wih1, Whh1, bih1, bhh1, Wfc, bfc, out);
}

// round 6
// speedup vs baseline: 1.0019x; 1.0019x over previous
#include <cuda_runtime.h>
#include <cstddef>

#define SEQ   512
#define BATCH 4096
#define INDIM 9
#define HID   64
#define OUTD  10
#define NTH   128
#define CSCALE 2.885390081777927f      // 2/ln2
#define WSCALE (-2.0f * CSCALE)

// shared memory float offsets
#define O_HIST  0                          // (SEQ+2)*HID : xw' rows -> r2 history; rows 512,513 dummy
#define O_XS    (O_HIST + (SEQ+2)*HID)     // SEQ*INDIM
#define O_R1    (O_XS + SEQ*INDIM)         // 4*HID ring (rows 0..3)
#define O_R2    (O_R1 + 4*HID)             // 2*HID
#define O_PI    (O_R2 + 2*HID)             // [2][64] ull = 256 floats
#define O_RS1   (O_PI + 256)               // HID
#define O_WFC   (O_RS1 + HID)              // OUTD*HID (scaled by -2)
#define O_BFC   (O_WFC + OUTD*HID)         // 16
#define SM_FLOATS (O_BFC + 16)
#define SM_BYTES  (SM_FLOATS * 4)

typedef unsigned long long ull;

__device__ __forceinline__ ull ffma2(ull a, ull b, ull c) {
    ull d; asm("fma.rn.f32x2 %0, %1, %2, %3;" : "=l"(d) : "l"(a), "l"(b), "l"(c));
    return d;
}
__device__ __forceinline__ ull fadd2(ull a, ull b) {
    ull d; asm("add.rn.f32x2 %0, %1, %2;" : "=l"(d) : "l"(a), "l"(b));
    return d;
}
__device__ __forceinline__ float f2sum(ull a) {
    float2 f = *reinterpret_cast<float2*>(&a);
    return f.x + f.y;
}
__device__ __forceinline__ ull pack2(float x, float y) {
    ull r; asm("mov.b64 %0, {%1,%2};" : "=l"(r) : "f"(x), "f"(y));
    return r;
}
// r = 1/(e^{2s}+1) with input pre-scaled by 2/ln2; tanh(s) = 1 - 2r
__device__ __forceinline__ float sig_r(float in) {
    float e, r;
    asm("ex2.approx.f32 %0, %1;" : "=f"(e) : "f"(in));
    asm("rcp.approx.f32 %0, %1;" : "=f"(r) : "f"(e + 1.0f));
    return r;
}
#define BAR128() asm volatile("bar.sync 0, 128;" ::: "memory")

// L1 phase body: r1dst = sig(w1 . r1src + xw'); *pidst = wi2A . r1src[0:32]
__device__ __forceinline__ void l1_step(const ull* __restrict__ w1,
                                        const ull* __restrict__ wi2,
                                        const float* __restrict__ r1src,
                                        const float* __restrict__ xwp,
                                        float* __restrict__ r1dst,
                                        ull* __restrict__ pidst) {
    const float xw = *xwp;
    const ulonglong2* hp = reinterpret_cast<const ulonglong2*>(r1src);
    ull a0=0,a1=0,a2=0,a3=0,a4=0,a5=0,a6=0,a7=0;   // critical dot: depth 4
    ull b0=0,b1=0,b2=0,b3=0;                        // offload half-dot
    #pragma unroll
    for (int q = 0; q < 8; ++q) {
        ulonglong2 u = hp[q];
        const int o = (q & 1) * 4;
        a0 = ffma2(u.x, w1[2*q],   a0);
        a1 = ffma2(u.y, w1[2*q+1], a1);
        b0 = ffma2(u.x, wi2[2*q],   b0);
        b1 = ffma2(u.y, wi2[2*q+1], b1);
        (void)o;
    }
    #pragma unroll
    for (int q = 8; q < 16; ++q) {
        ulonglong2 u = hp[q];
        a2 = ffma2(u.x, w1[2*q],   a2);
        a3 = ffma2(u.y, w1[2*q+1], a3);
        a4 = ffma2(u.x, w1[2*q],   0ull);   // placeholder removed below
        (void)a4;
        a4 = 0ull;
        break;
    }
    // (restructured cleanly below)
    ull c0=0,c1=0,c2=0,c3=0;
    #pragma unroll
    for (int q = 8; q < 16; ++q) {
        ulonglong2 u = hp[q];
        c0 = ffma2(u.x, w1[2*q],   c0);
        c1 = ffma2(u.y, w1[2*q+1], c1);
    }
    ull sa = fadd2(fadd2(a0, c0), fadd2(a1, c1));
    *r1dst = sig_r(f2sum(sa) + xw);
    b2 = fadd2(b0, b1);
    *pidst = b2;
    (void)a5;(void)a6;(void)a7;(void)b3;(void)c2;(void)c3;
}

// L2 phase body: r2 = sig(base2 + piA + wi2B.r1half + wh.r2src)
__device__ __forceinline__ void l2_step(const ull* __restrict__ wh,
                                        const ull* __restrict__ wi2,
                                        const float* __restrict__ r2src,
                                        const float* __restrict__ r1h,
                                        const ull* __restrict__ pisrc,
                                        float base2,
                                        float* __restrict__ r2dst,
                                        float* __restrict__ histdst) {
    const ull piA = *pisrc;
    const ulonglong2* hp = reinterpret_cast<const ulonglong2*>(r2src);
    const ulonglong2* hq = reinterpret_cast<const ulonglong2*>(r1h);
    ull c0=0,c1=0,c2=0,c3=0, d0=0,d1=0;
    #pragma unroll
    for (int q = 0; q < 8; ++q) {
        ulonglong2 u = hp[q];
        c0 = ffma2(u.x, wh[2*q],   c0);
        c1 = ffma2(u.y, wh[2*q+1], c1);
    }
    #pragma unroll
    for (int q = 8; q < 16; ++q) {
        ulonglong2 u = hp[q];
        c2 = ffma2(u.x, wh[2*q],   c2);
        c3 = ffma2(u.y, wh[2*q+1], c3);
    }
    #pragma unroll
    for (int q = 0; q < 8; ++q) {
        ulonglong2 u = hq[q];
        d0 = ffma2(u.x, wi2[2*q],   d0);
        d1 = ffma2(u.y, wi2[2*q+1], d1);
    }
    ull sc = fadd2(fadd2(c0, c2), fadd2(c1, c3));
    ull sd = fadd2(fadd2(d0, d1), piA);
    float r = sig_r(f2sum(fadd2(sc, sd)) + base2);
    *r2dst   = r;
    *histdst = r;
}

__global__ __launch_bounds__(NTH, 1)
void rnn_motion_kernel(const float* __restrict__ x,
                       const float* __restrict__ Wih0, const float* __restrict__ Whh0,
                       const float* __restrict__ bih0, const float* __restrict__ bhh0,
                       const float* __restrict__ Wih1, const float* __restrict__ Whh1,
                       const float* __restrict__ bih1, const float* __restrict__ bhh1,
                       const float* __restrict__ Wfc,  const float* __restrict__ bfc_g,
                       float* __restrict__ out)
{
    extern __shared__ float sm[];
    float* hist = sm + O_HIST;
    float* xs   = sm + O_XS;
    float* R    = sm + O_R1;                           // ring, 4 rows
    float* r2b  = sm + O_R2;
    ull*   pib  = reinterpret_cast<ull*>(sm + O_PI);   // [2][64]
    float* rs1  = sm + O_RS1;
    float* wfc  = sm + O_WFC;
    float* bfc  = sm + O_BFC;

    const int tid = threadIdx.x;

    // ---- prologue A ----
    for (int e = tid; e < SEQ*INDIM; e += NTH) {
        int t = e / INDIM, k = e % INDIM;
        xs[e] = x[((size_t)t * BATCH + (BATCH - 1)) * INDIM + k];
    }
    for (int e = tid; e < OUTD*HID; e += NTH) wfc[e] = -2.0f * Wfc[e];
    hist[SEQ*HID + tid] = 0.0f;                         // dummy rows 512,513
    for (int e = tid; e < 6*HID; e += NTH) R[e] = 0.5f; // ring rows 0..3 + r2 both parities
    if (tid < HID) {
        const float4* p = reinterpret_cast<const float4*>(Whh0 + (size_t)tid * HID);
        float s = 0.f;
        #pragma unroll
        for (int q = 0; q < 16; ++q) { float4 v = p[q]; s += (v.x+v.y)+(v.z+v.w); }
        rs1[tid] = s;                                   // rowsum(Whh0_i)
    }
    if (tid < OUTD) {                                   // bfc'[o] = bfc + rowsum(Wfc_o)
        const float4* p = reinterpret_cast<const float4*>(Wfc + (size_t)tid * HID);
        float s = bfc_g[tid];
        #pragma unroll
        for (int q = 0; q < 16; ++q) { float4 v = p[q]; s += (v.x+v.y)+(v.z+v.w); }
        bfc[tid] = s;
    }
    __syncthreads();

    // ---- prologue B: xw'[t][i] = C*(x_t.Wih0_i + b_ih0 + b_hh0 + rowsum(Whh0_i)) ----
    {
        const int ii = tid & (HID-1);
        float wi[INDIM];
        #pragma unroll
        for (int k = 0; k < INDIM; ++k) wi[k] = CSCALE * Wih0[ii*INDIM + k];
        const float bb = CSCALE * (bih0[ii] + bhh0[ii] + rs1[ii]);
        for (int t = tid >> 6; t < SEQ; t += NTH/HID) {
            float s = bb;
            #pragma unroll
            for (int k = 0; k < INDIM; ++k) s += xs[t*INDIM + k] * wi[k];
            hist[t*HID + ii] = s;
        }
    }
    __syncthreads();

    // ---- pipelined scan: phases it = 0..513, one BAR each ----
    if (tid < HID) {
        // ===== layer1 warps: r1 recurrence (ring) + first-half pI offload =====
        const int i = tid;
        ull w1[32], wi2[16];
        {
            const float4* p = reinterpret_cast<const float4*>(Whh0 + (size_t)i * HID);
            #pragma unroll
            for (int q = 0; q < 16; ++q) {
                float4 v = p[q];
                w1[2*q]   = pack2(v.x*WSCALE, v.y*WSCALE);
                w1[2*q+1] = pack2(v.z*WSCALE, v.w*WSCALE);
            }
            const float4* p2 = reinterpret_cast<const float4*>(Wih1 + (size_t)i * HID);
            #pragma unroll
            for (int q = 0; q < 8; ++q) {          // cols [0:32]
                float4 v = p2[q];
                wi2[2*q]   = pack2(v.x*WSCALE, v.y*WSCALE);
                wi2[2*q+1] = pack2(v.z*WSCALE, v.w*WSCALE);
            }
        }
        const float* xwp = hist + i;
        // peel phases 0,1
        l1_step(w1, wi2, R+3*HID, xwp, R+0*HID+i, &pib[i]);      BAR128(); xwp += HID;
        l1_step(w1, wi2, R+0*HID, xwp, R+1*HID+i, &pib[64+i]);   BAR128(); xwp += HID;
        #pragma unroll 1
        for (int k = 0; k < 128; ++k) {  // phases 2..513
            l1_step(w1, wi2, R+1*HID, xwp, R+2*HID+i, &pib[i]);    BAR128(); xwp += HID;
            l1_step(w1, wi2, R+2*HID, xwp, R+3*HID+i, &pib[64+i]); BAR128(); xwp += HID;
            l1_step(w1, wi2, R+3*HID, xwp, R+0*HID+i, &pib[i]);    BAR128(); xwp += HID;
            l1_step(w1, wi2, R+0*HID, xwp, R+1*HID+i, &pib[64+i]); BAR128(); xwp += HID;
        }
    } else {
        // ===== layer2 warps: r2 recurrence, second-half pI inline from ring =====
        const int i = tid - HID;
        ull wh[32], wi2[16];
        float rsH = 0.f, rsI = 0.f;
        {
            const float4* p = reinterpret_cast<const float4*>(Whh1 + (size_t)i * HID);
            #pragma unroll
            for (int q = 0; q < 16; ++q) {
                float4 v = p[q];
                rsH += (v.x+v.y)+(v.z+v.w);
                wh[2*q]   = pack2(v.x*WSCALE, v.y*WSCALE);
                wh[2*q+1] = pack2(v.z*WSCALE, v.w*WSCALE);
            }
            const float4* p2 = reinterpret_cast<const float4*>(Wih1 + (size_t)i * HID);
            #pragma unroll
            for (int q = 0; q < 16; ++q) {
                float4 v = p2[q];
                rsI += (v.x+v.y)+(v.z+v.w);
                if (q >= 8) {                      // cols [32:64]
                    wi2[2*(q-8)]   = pack2(v.x*WSCALE, v.y*WSCALE);
                    wi2[2*(q-8)+1] = pack2(v.z*WSCALE, v.w*WSCALE);
                }
            }
        }
        const float base2 = CSCALE * (bih1[i] + bhh1[i] + rsI + rsH);
        BAR128(); BAR128();                        // phases 0,1 (warm-up)
        float* hw = hist + i;
        #pragma unroll 1
        for (int k = 0; k < 128; ++k) {  // phases 2..513, s = phase-2
            l2_step(wh, wi2, r2b+HID, R+0*HID+32, &pib[64+i], base2, r2b+i,     hw); BAR128(); hw += HID;
            l2_step(wh, wi2, r2b,     R+1*HID+32, &pib[i],    base2, r2b+HID+i, hw); BAR128(); hw += HID;
            l2_step(wh, wi2, r2b+HID, R+2*HID+32, &pib[64+i], base2, r2b+i,     hw); BAR128(); hw += HID;
            l2_step(wh, wi2, r2b,     R+3*HID+32, &pib[i],    base2, r2b+HID+i, hw); BAR128(); hw += HID;
        }
    }
    __syncthreads();

    // ---- epilogue: out[t][o] = bfc'[o] + sum_k r2[t][k] * (-2*Wfc[o][k]) ----
    #pragma unroll
    for (int m = 0; m < SEQ/NTH; ++m) {
        const int t = tid + NTH * m;
        const float4* h4 = reinterpret_cast<const float4*>(hist + t*HID);
        #pragma unroll
        for (int o = 0; o < OUTD; ++o) {
            const float4* w4 = reinterpret_cast<const float4*>(wfc + o*HID);
            float s0 = bfc[o], s1 = 0.f, s2 = 0.f, s3 = 0.f;
            #pragma unroll
            for (int q = 0; q < HID/4; ++q) {
                float4 h = h4[q], w = w4[q];
                s0 = fmaf(h.x, w.x, s0);
                s1 = fmaf(h.y, w.y, s1);
                s2 = fmaf(h.z, w.z, s2);
                s3 = fmaf(h.w, w.w, s3);
            }
            out[t*OUTD + o] = (s0 + s1) + (s2 + s3);
        }
    }
}

extern "C" void kernel_launch(void* const* d_in, const int* in_sizes, int n_in,
                              void* d_out, int out_size) {
    (void)in_sizes; (void)n_in; (void)out_size;
    const float* x    = (const float*)d_in[0];
    const float* Wih0 = (const float*)d_in[1];
    const float* Whh0 = (const float*)d_in[2];
    const float* bih0 = (const float*)d_in[3];
    const float* bhh0 = (const float*)d_in[4];
    const float* Wih1 = (const float*)d_in[5];
    const float* Whh1 = (const float*)d_in[6];
    const float* bih1 = (const float*)d_in[7];
    const float* bhh1 = (const float*)d_in[8];
    const float* Wfc  = (const float*)d_in[9];
    const float* bfc  = (const float*)d_in[10];
    float* out = (float*)d_out;

    cudaFuncSetAttribute(rnn_motion_kernel,
                         cudaFuncAttributeMaxDynamicSharedMemorySize, SM_BYTES);
    rnn_motion_kernel<<<1, NTH, SM_BYTES>>>(
        x, Wih0, Whh0, bih0, bhh0, Wih1, Whh1, bih1, bhh1, Wfc, bfc, out);
}